// round 1
// baseline (speedup 1.0000x reference)
#include <cuda_runtime.h>
#include <cstdint>
#include <cstddef>

#define Nn 50000
#define Ee 300000
#define DH 256

// ---------------- scratch (static device globals; no allocation) ----------------
__device__ float g_h  [(size_t)Nn * DH];   // node features (layer input / residual)
__device__ float g_h1 [(size_t)Nn * DH];   // h @ W  (per hop)
__device__ float g_agg[(size_t)Nn * DH];   // GAT aggregation output
__device__ float g_acc[(size_t)Nn * DH];   // decayed hop accumulator
__device__ float g_as [(size_t)Nn * 8];    // alpha_src per (node, head)
__device__ float g_ad [(size_t)Nn * 8];    // alpha_dst per (node, head)
__device__ float g_m  [(size_t)Nn * 8];    // segment max
__device__ float g_s  [(size_t)Nn * 8];    // segment sum
__device__ float g_e  [(size_t)Ee * 8];    // per-edge attention scratch

// ---------------- GEMM: C[M,256] = epi(A[M,256] (+abias) @ B[256,256] + bbias) ----
// mode bit0: leaky_relu(0.01) ; mode bit1: C += scale*val (else C = scale*val)
__global__ void __launch_bounds__(256) gemm128(
    const float* __restrict__ A, const float* __restrict__ B,
    const float* __restrict__ abias, const float* __restrict__ bbias,
    float* __restrict__ C, int M, int mode, float scale)
{
    __shared__ float As[16][128];
    __shared__ float Bs[16][128];

    const int tid = threadIdx.x;
    const int tx = tid & 15;        // col group (8 cols)
    const int ty = tid >> 4;        // row group (8 rows)
    const int rowBase = blockIdx.x * 128;
    const int colBase = blockIdx.y * 128;

    const int ar = tid >> 1;            // 0..127 (row in A tile)
    const int ak = (tid & 1) * 8;       // 0 or 8 (k offset)
    const int bk = tid >> 4;            // 0..15 (k row in B tile)
    const int bn = (tid & 15) * 8;      // col offset in B tile
    const int grow = rowBase + ar;

    float acc[8][8];
#pragma unroll
    for (int i = 0; i < 8; i++)
#pragma unroll
        for (int j = 0; j < 8; j++) acc[i][j] = 0.f;

    for (int kt = 0; kt < 256; kt += 16) {
        float4 a0 = make_float4(0.f, 0.f, 0.f, 0.f);
        float4 a1 = a0;
        if (grow < M) {
            const float* ap = A + (size_t)grow * 256 + kt + ak;
            a0 = *(const float4*)ap;
            a1 = *(const float4*)(ap + 4);
        }
        if (abias) {
            const float* bp = abias + kt + ak;
            a0.x += bp[0]; a0.y += bp[1]; a0.z += bp[2]; a0.w += bp[3];
            a1.x += bp[4]; a1.y += bp[5]; a1.z += bp[6]; a1.w += bp[7];
        }
        As[ak + 0][ar] = a0.x; As[ak + 1][ar] = a0.y;
        As[ak + 2][ar] = a0.z; As[ak + 3][ar] = a0.w;
        As[ak + 4][ar] = a1.x; As[ak + 5][ar] = a1.y;
        As[ak + 6][ar] = a1.z; As[ak + 7][ar] = a1.w;

        const float* Bp = B + (size_t)(kt + bk) * 256 + colBase + bn;
        *(float4*)&Bs[bk][bn]     = *(const float4*)Bp;
        *(float4*)&Bs[bk][bn + 4] = *(const float4*)(Bp + 4);

        __syncthreads();
#pragma unroll
        for (int k = 0; k < 16; k++) {
            float4 av0 = *(float4*)&As[k][ty * 8];
            float4 av1 = *(float4*)&As[k][ty * 8 + 4];
            float4 bv0 = *(float4*)&Bs[k][tx * 8];
            float4 bv1 = *(float4*)&Bs[k][tx * 8 + 4];
            float a[8] = {av0.x, av0.y, av0.z, av0.w, av1.x, av1.y, av1.z, av1.w};
            float b[8] = {bv0.x, bv0.y, bv0.z, bv0.w, bv1.x, bv1.y, bv1.z, bv1.w};
#pragma unroll
            for (int i = 0; i < 8; i++)
#pragma unroll
                for (int j = 0; j < 8; j++)
                    acc[i][j] += a[i] * b[j];
        }
        __syncthreads();
    }

#pragma unroll
    for (int i = 0; i < 8; i++) {
        int r = rowBase + ty * 8 + i;
        if (r >= M) continue;
#pragma unroll
        for (int jj = 0; jj < 2; jj++) {
            float4 o;
            float* ov = &o.x;
#pragma unroll
            for (int j = 0; j < 4; j++) {
                int c = colBase + tx * 8 + jj * 4 + j;
                float v = acc[i][jj * 4 + j];
                if (bbias) v += bbias[c];
                if (mode & 1) v = (v > 0.f) ? v : 0.01f * v;
                ov[j] = v * scale;
            }
            float* dp = C + (size_t)r * 256 + colBase + tx * 8 + jj * 4;
            if (mode & 2) {
                float4 p = *(float4*)dp;
                o.x += p.x; o.y += p.y; o.z += p.z; o.w += p.w;
            }
            *(float4*)dp = o;
        }
    }
}

// ---------------- per-node attention logits: warp per node ----------------
__global__ void alpha_kernel(const float* __restrict__ h1,
                             const float* __restrict__ asrc,
                             const float* __restrict__ adst)
{
    int gt = blockIdx.x * blockDim.x + threadIdx.x;
    int w = gt >> 5;
    int lane = gt & 31;
    if (w >= Nn) return;
    const float* row = h1 + (size_t)w * 256;
#pragma unroll
    for (int h = 0; h < 8; h++) {
        float v = row[h * 32 + lane];
        float vs = v * asrc[h * 32 + lane];
        float vd = v * adst[h * 32 + lane];
#pragma unroll
        for (int o = 16; o > 0; o >>= 1) {
            vs += __shfl_xor_sync(0xffffffffu, vs, o);
            vd += __shfl_xor_sync(0xffffffffu, vd, o);
        }
        if (lane == 0) { g_as[w * 8 + h] = vs; g_ad[w * 8 + h] = vd; }
    }
}

// ---------------- init m=-inf, s=0, agg=0 ----------------
__global__ void init_kernel()
{
    int i = blockIdx.x * blockDim.x + threadIdx.x;
    float4 z = make_float4(0.f, 0.f, 0.f, 0.f);
    if (i < Nn * 64) ((float4*)g_agg)[i] = z;
    if (i < Nn * 2) {
        ((float4*)g_s)[i] = z;
        float mi = __int_as_float(0xff800000);
        ((float4*)g_m)[i] = make_float4(mi, mi, mi, mi);
    }
}

__device__ __forceinline__ void atomicMaxF(float* a, float v)
{
    if (v >= 0.f) atomicMax((int*)a, __float_as_int(v));
    else          atomicMin((unsigned int*)a, __float_as_uint(v));
}

// ---------------- edge pass 1: e = leaky(as[src]+ad[dst], 0.2); segment max ----
__global__ void edge1_kernel(const int* __restrict__ src, const int* __restrict__ dst)
{
    int e = blockIdx.x * blockDim.x + threadIdx.x;
    if (e >= Ee) return;
    int s = src[e], d = dst[e];
    const float4* aps = (const float4*)(g_as + (size_t)s * 8);
    const float4* apd = (const float4*)(g_ad + (size_t)d * 8);
    float4 s0 = aps[0], s1 = aps[1];
    float4 d0 = apd[0], d1 = apd[1];
    float v[8] = {s0.x + d0.x, s0.y + d0.y, s0.z + d0.z, s0.w + d0.w,
                  s1.x + d1.x, s1.y + d1.y, s1.z + d1.z, s1.w + d1.w};
    float* mrow = g_m + (size_t)d * 8;
#pragma unroll
    for (int h = 0; h < 8; h++) {
        float t = (v[h] > 0.f) ? v[h] : 0.2f * v[h];
        v[h] = t;
        atomicMaxF(mrow + h, t);
    }
    float4* ep = (float4*)(g_e + (size_t)e * 8);
    ep[0] = make_float4(v[0], v[1], v[2], v[3]);
    ep[1] = make_float4(v[4], v[5], v[6], v[7]);
}

// ---------------- edge pass 2: e = exp(e - m[dst]); segment sum ----------------
__global__ void edge2_kernel(const int* __restrict__ dst)
{
    int e = blockIdx.x * blockDim.x + threadIdx.x;
    if (e >= Ee) return;
    int d = dst[e];
    float4* ep = (float4*)(g_e + (size_t)e * 8);
    float4 e0 = ep[0], e1 = ep[1];
    const float4* mp = (const float4*)(g_m + (size_t)d * 8);
    float4 m0 = mp[0], m1 = mp[1];
    float v[8] = {__expf(e0.x - m0.x), __expf(e0.y - m0.y),
                  __expf(e0.z - m0.z), __expf(e0.w - m0.w),
                  __expf(e1.x - m1.x), __expf(e1.y - m1.y),
                  __expf(e1.z - m1.z), __expf(e1.w - m1.w)};
    float* srow = g_s + (size_t)d * 8;
#pragma unroll
    for (int h = 0; h < 8; h++) atomicAdd(srow + h, v[h]);
    ep[0] = make_float4(v[0], v[1], v[2], v[3]);
    ep[1] = make_float4(v[4], v[5], v[6], v[7]);
}

// ---------------- edge pass 3: scatter messages; warp per edge ----------------
__global__ void edge3_kernel(const int* __restrict__ src, const int* __restrict__ dst)
{
    int gt = blockIdx.x * blockDim.x + threadIdx.x;
    int e = gt >> 5;
    int lane = gt & 31;
    if (e >= Ee) return;
    int s = src[e], d = dst[e];
    int c0 = lane * 4;
    int c1 = 128 + lane * 4;
    int h0 = lane >> 3;
    int h1 = 4 + (lane >> 3);
    float a0 = g_e[(size_t)e * 8 + h0] / (g_s[(size_t)d * 8 + h0] + 1e-16f);
    float a1 = g_e[(size_t)e * 8 + h1] / (g_s[(size_t)d * 8 + h1] + 1e-16f);
    const float* hs = g_h1 + (size_t)s * 256;
    float* ag = g_agg + (size_t)d * 256;
    float4 v0 = *(const float4*)(hs + c0);
    float4 v1 = *(const float4*)(hs + c1);
    v0.x *= a0; v0.y *= a0; v0.z *= a0; v0.w *= a0;
    v1.x *= a1; v1.y *= a1; v1.z *= a1; v1.w *= a1;
    atomicAdd((float4*)(ag + c0), v0);   // vectorized RED, sm_90+
    atomicAdd((float4*)(ag + c1), v1);
}

// ---------------- layernorm + residual: warp per node ----------------
__global__ void ln_kernel(const float* __restrict__ acc,
                          const float* __restrict__ scale,
                          const float* __restrict__ bias,
                          const float* __restrict__ res,
                          float* __restrict__ out)
{
    int gt = blockIdx.x * blockDim.x + threadIdx.x;
    int n = gt >> 5;
    int lane = gt & 31;
    if (n >= Nn) return;
    const float* a = acc + (size_t)n * 256;
    float4 v0 = *(const float4*)(a + lane * 4);
    float4 v1 = *(const float4*)(a + 128 + lane * 4);
    float sm = v0.x + v0.y + v0.z + v0.w + v1.x + v1.y + v1.z + v1.w;
    float sq = v0.x * v0.x + v0.y * v0.y + v0.z * v0.z + v0.w * v0.w
             + v1.x * v1.x + v1.y * v1.y + v1.z * v1.z + v1.w * v1.w;
#pragma unroll
    for (int o = 16; o > 0; o >>= 1) {
        sm += __shfl_xor_sync(0xffffffffu, sm, o);
        sq += __shfl_xor_sync(0xffffffffu, sq, o);
    }
    float mu = sm * (1.f / 256.f);
    float var = sq * (1.f / 256.f) - mu * mu;
    float rstd = rsqrtf(var + 1e-5f);

    const float* rp = res + (size_t)n * 256;
    float4 r0 = *(const float4*)(rp + lane * 4);
    float4 r1 = *(const float4*)(rp + 128 + lane * 4);
    float4 sc0 = *(const float4*)(scale + lane * 4);
    float4 sc1 = *(const float4*)(scale + 128 + lane * 4);
    float4 b0 = *(const float4*)(bias + lane * 4);
    float4 b1 = *(const float4*)(bias + 128 + lane * 4);

    float4 o0, o1;
    o0.x = (v0.x - mu) * rstd * sc0.x + b0.x + r0.x;
    o0.y = (v0.y - mu) * rstd * sc0.y + b0.y + r0.y;
    o0.z = (v0.z - mu) * rstd * sc0.z + b0.z + r0.z;
    o0.w = (v0.w - mu) * rstd * sc0.w + b0.w + r0.w;
    o1.x = (v1.x - mu) * rstd * sc1.x + b1.x + r1.x;
    o1.y = (v1.y - mu) * rstd * sc1.y + b1.y + r1.y;
    o1.z = (v1.z - mu) * rstd * sc1.z + b1.z + r1.z;
    o1.w = (v1.w - mu) * rstd * sc1.w + b1.w + r1.w;

    float* op = out + (size_t)n * 256;
    *(float4*)(op + lane * 4) = o0;
    *(float4*)(op + 128 + lane * 4) = o1;
}

// ---------------- host driver ----------------
extern "C" void kernel_launch(void* const* d_in, const int* in_sizes, int n_in,
                              void* d_out, int out_size)
{
    const float* x        = (const float*)d_in[0];
    const int*   edges    = (const int*)  d_in[1];
    const float* lin1_w   = (const float*)d_in[2];
    const float* lin1_b   = (const float*)d_in[3];
    const float* gat_w    = (const float*)d_in[4];
    const float* att_src  = (const float*)d_in[5];
    const float* att_dst  = (const float*)d_in[6];
    const float* gat_bias = (const float*)d_in[7];
    const float* dec_w    = (const float*)d_in[8];
    const float* dec_b    = (const float*)d_in[9];
    const float* ln_scale = (const float*)d_in[10];
    const float* ln_bias  = (const float*)d_in[11];
    float* out = (float*)d_out;

    static const float DECAY[3] = {1.0f, 0.60653065971263342f, 0.36787944117144233f};

    float *p_h, *p_h1, *p_agg, *p_acc;
    cudaGetSymbolAddress((void**)&p_h,   g_h);
    cudaGetSymbolAddress((void**)&p_h1,  g_h1);
    cudaGetSymbolAddress((void**)&p_agg, g_agg);
    cudaGetSymbolAddress((void**)&p_acc, g_acc);

    dim3 gg((Nn + 127) / 128, 2);

    // h = leaky(x @ lin1_w + lin1_b, 0.01)
    gemm128<<<gg, 256>>>(x, lin1_w, nullptr, lin1_b, p_h, Nn, 1, 1.f);

    for (int l = 0; l < 2; l++) {
        for (int k = 0; k < 3; k++) {
            int lk = l * 3 + k;
            // h1 = h @ W
            gemm128<<<gg, 256>>>(p_h, gat_w + (size_t)lk * 65536,
                                 nullptr, nullptr, p_h1, Nn, 0, 1.f);
            alpha_kernel<<<(Nn * 32 + 255) / 256, 256>>>(
                p_h1, att_src + (size_t)lk * 256, att_dst + (size_t)lk * 256);
            init_kernel<<<(Nn * 64 + 255) / 256, 256>>>();

            const int* src = edges + (size_t)k * 2 * Ee;
            const int* dst = src + Ee;
            edge1_kernel<<<(Ee + 255) / 256, 256>>>(src, dst);
            edge2_kernel<<<(Ee + 255) / 256, 256>>>(dst);
            edge3_kernel<<<(Ee * 32 + 255) / 256, 256>>>(src, dst);

            // acc (k==0: =, else: +=) decay * leaky((agg + gat_bias) @ dec_w + dec_b)
            int mode = 1 | (k > 0 ? 2 : 0);
            gemm128<<<gg, 256>>>(p_agg, dec_w + (size_t)lk * 65536,
                                 gat_bias + (size_t)lk * 256,
                                 dec_b + (size_t)lk * 256,
                                 p_acc, Nn, mode, DECAY[k]);
        }
        // h = LN(acc)*scale+bias + residual(h); layer 1 writes final output
        ln_kernel<<<(Nn * 32 + 255) / 256, 256>>>(
            p_acc, ln_scale + (size_t)l * 256, ln_bias + (size_t)l * 256,
            p_h, (l == 0) ? p_h : out);
    }
}

// round 3
// speedup vs baseline: 1.4504x; 1.4504x over previous
#include <cuda_runtime.h>
#include <cuda_bf16.h>
#include <cstdint>
#include <cstddef>

#define Nn 50000
#define Ee 300000
#define DH 256

// ================= helpers =================
__device__ __forceinline__ uint32_t smem_to_u32(const void* p) {
    uint32_t a;
    asm("{ .reg .u64 t; cvta.to.shared.u64 t, %1; cvt.u32.u64 %0, t; }" : "=r"(a) : "l"(p));
    return a;
}
__device__ __forceinline__ void ldsm4(uint32_t* r, uint32_t addr) {
    asm volatile("ldmatrix.sync.aligned.m8n8.x4.shared.b16 {%0,%1,%2,%3}, [%4];"
        : "=r"(r[0]), "=r"(r[1]), "=r"(r[2]), "=r"(r[3]) : "r"(addr));
}
__device__ __forceinline__ void ldsm2(uint32_t* r, uint32_t addr) {
    asm volatile("ldmatrix.sync.aligned.m8n8.x2.shared.b16 {%0,%1}, [%2];"
        : "=r"(r[0]), "=r"(r[1]) : "r"(addr));
}
__device__ __forceinline__ void mma16816(float* c, const uint32_t* a, const uint32_t* b) {
    asm volatile("mma.sync.aligned.m16n8k16.row.col.f32.bf16.bf16.f32 "
        "{%0,%1,%2,%3}, {%4,%5,%6,%7}, {%8,%9}, {%0,%1,%2,%3};"
        : "+f"(c[0]), "+f"(c[1]), "+f"(c[2]), "+f"(c[3])
        : "r"(a[0]), "r"(a[1]), "r"(a[2]), "r"(a[3]), "r"(b[0]), "r"(b[1]));
}
#define SMEM_SWZ(o) ((o) ^ ((((uint32_t)(o)) >> 3) & 0x70u))

// ================= scratch (static device globals) =================
__device__ float g_h  [(size_t)Nn * DH];
__device__ float g_h1 [(size_t)Nn * DH];
__device__ float g_agg[(size_t)Nn * DH];
__device__ float g_acc[(size_t)Nn * DH];
__device__ float g_as [(size_t)Nn * 8];
__device__ float g_ad [(size_t)Nn * 8];
__device__ float g_m  [(size_t)Nn * 8];
__device__ float g_s  [(size_t)Nn * 8];
__device__ float g_e  [(size_t)Ee * 8];
// pre-converted weights: 13 matrices, [4 kchunks][256 n][64 k] bf16, SW128 swizzle baked in
__device__ __nv_bfloat16 g_bh[13 * 65536];
__device__ __nv_bfloat16 g_bl[13 * 65536];

// ---------------- weight convert: W[k][n] fp32 -> W^T swizzled bf16 hi/lo ------
__global__ void convw_kernel(const float* __restrict__ W, int nmat, int gbase)
{
    int id = blockIdx.x * blockDim.x + threadIdx.x;
    if (id >= nmat * 65536) return;
    int g = id >> 16;
    int r = id & 65535;
    int n = r & 255;
    int kf = r >> 8;
    float v = W[(size_t)g * 65536 + (size_t)kf * 256 + n];
    __nv_bfloat16 hi = __float2bfloat16(v);
    __nv_bfloat16 lo = __float2bfloat16(v - __bfloat162float(hi));
    int kc = kf >> 6, kk = kf & 63;
    uint32_t off = (uint32_t)kc * 32768u + SMEM_SWZ((uint32_t)(n * 128 + kk * 2));
    size_t base = (size_t)(gbase + g) * 131072u;
    *(__nv_bfloat16*)((char*)g_bh + base + off) = hi;
    *(__nv_bfloat16*)((char*)g_bl + base + off) = lo;
}

// ---------------- mma.sync GEMM: C[M,256] = epi((A+abias) @ W[gidx] + bbias) ------
// mode bit0: leaky(0.01); bit1: C += scale*v (else =); bit2: emit attention alphas
#define SM_AH 0
#define SM_AL 16384
#define SM_BH 32768
#define SM_BL 49152
#define SM_TOTAL 65536

__global__ void __launch_bounds__(256) gemm_mma(
    const float* __restrict__ A, int gidx,
    const float* __restrict__ abias, const float* __restrict__ bbias,
    const float* __restrict__ attS, const float* __restrict__ attD,
    float* __restrict__ C, int M, int mode, float scale)
{
    extern __shared__ char smem[];
    const uint32_t sb = smem_to_u32(smem);
    const int tid = threadIdx.x, wid = tid >> 5, lane = tid & 31;
    const int rowBase = blockIdx.x * 128;
    const int colBase = blockIdx.y * 128;
    const int warpM = (wid & 1) * 64;
    const int warpN = (wid >> 1) * 32;

    const char* bh = (const char*)g_bh + (size_t)gidx * 131072u + (size_t)colBase * 128u;
    const char* bl = (const char*)g_bl + (size_t)gidx * 131072u + (size_t)colBase * 128u;

    float acc[4][4][4];
#pragma unroll
    for (int i = 0; i < 4; i++)
#pragma unroll
        for (int j = 0; j < 4; j++)
#pragma unroll
            for (int c = 0; c < 4; c++) acc[i][j][c] = 0.f;

    // per-thread ldmatrix address pieces
    const uint32_t xorA = (uint32_t)((lane & 7) << 4);
    const uint32_t aRow = (uint32_t)(warpM + (lane & 15));
    const uint32_t aSel = (uint32_t)((lane >> 4) << 4);      // 0 or 16
    const uint32_t bRow = (uint32_t)(warpN + (lane & 7));
    const uint32_t bSel = (uint32_t)(((lane >> 3) & 1) << 4); // 0 or 16

    for (int kc = 0; kc < 4; kc++) {
        if (kc > 0) __syncthreads();
        // ---- fill A hi/lo (fp32 -> split bf16, SW128-swizzled [128 rows][64 k]) ----
        const int abase = kc * 64;
#pragma unroll
        for (int it = 0; it < 8; it++) {
            int idx = tid + it * 256;       // 0..2047
            int r = idx >> 4;               // row 0..127
            int kq = (idx & 15) * 4;        // k offset 0..60
            float4 v = make_float4(0.f, 0.f, 0.f, 0.f);
            int gr = rowBase + r;
            if (gr < M) v = *(const float4*)(A + (size_t)gr * 256 + abase + kq);
            if (abias) {
                const float* bp = abias + abase + kq;
                v.x += bp[0]; v.y += bp[1]; v.z += bp[2]; v.w += bp[3];
            }
            __nv_bfloat162 h0, h1p, l0, l1p;
            h0.x = __float2bfloat16(v.x);  h0.y = __float2bfloat16(v.y);
            h1p.x = __float2bfloat16(v.z); h1p.y = __float2bfloat16(v.w);
            l0.x = __float2bfloat16(v.x - __bfloat162float(h0.x));
            l0.y = __float2bfloat16(v.y - __bfloat162float(h0.y));
            l1p.x = __float2bfloat16(v.z - __bfloat162float(h1p.x));
            l1p.y = __float2bfloat16(v.w - __bfloat162float(h1p.y));
            uint32_t so = SMEM_SWZ((uint32_t)(r * 128 + kq * 2));
            uint2 uh, ul;
            uh.x = *(uint32_t*)&h0;  uh.y = *(uint32_t*)&h1p;
            ul.x = *(uint32_t*)&l0;  ul.y = *(uint32_t*)&l1p;
            *(uint2*)(smem + SM_AH + so) = uh;
            *(uint2*)(smem + SM_AL + so) = ul;
        }
        // ---- copy this CTA's B hi/lo columns (pre-swizzled, 16KB each) ----
        {
            const uint4* sh = (const uint4*)(bh + (size_t)kc * 32768);
            const uint4* sl = (const uint4*)(bl + (size_t)kc * 32768);
            uint4* dh = (uint4*)(smem + SM_BH);
            uint4* dl = (uint4*)(smem + SM_BL);
#pragma unroll
            for (int it = 0; it < 4; it++) {
                int j = tid + it * 256;
                dh[j] = sh[j];
                dl[j] = sl[j];
            }
        }
        __syncthreads();

        // ---- compute: 4 k16 steps, 3 split passes ----
#pragma unroll
        for (int ks = 0; ks < 4; ks++) {
            uint32_t ah[4][4], al[4][4], bhf[4][2], blf[4][2];
            const uint32_t kOffA = (uint32_t)(ks * 32) + aSel;
            const uint32_t kOffB = (uint32_t)(ks * 32) + bSel;
#pragma unroll
            for (int i = 0; i < 4; i++) {
                uint32_t off = (((aRow + i * 16) * 128u + kOffA) ^ xorA);
                ldsm4(ah[i], sb + SM_AH + off);
                ldsm4(al[i], sb + SM_AL + off);
            }
#pragma unroll
            for (int j = 0; j < 4; j++) {
                uint32_t off = (((bRow + j * 8) * 128u + kOffB) ^ xorA);
                ldsm2(bhf[j], sb + SM_BH + off);
                ldsm2(blf[j], sb + SM_BL + off);
            }
#pragma unroll
            for (int i = 0; i < 4; i++)
#pragma unroll
                for (int j = 0; j < 4; j++) mma16816(acc[i][j], ah[i], bhf[j]);
#pragma unroll
            for (int i = 0; i < 4; i++)
#pragma unroll
                for (int j = 0; j < 4; j++) mma16816(acc[i][j], ah[i], blf[j]);
#pragma unroll
            for (int i = 0; i < 4; i++)
#pragma unroll
                for (int j = 0; j < 4; j++) mma16816(acc[i][j], al[i], bhf[j]);
        }
    }

    // ---- epilogue ----
    const int tg = lane >> 2;            // row within 8-row group
    const int tc = (lane & 3) * 2;       // col pair within 8-col tile
    const int head = blockIdx.y * 4 + (wid >> 1);
#pragma unroll
    for (int i = 0; i < 4; i++) {
        int r0 = rowBase + warpM + i * 16 + tg;   // and r0+8
        float as0 = 0.f, ad0 = 0.f, as1 = 0.f, ad1 = 0.f;
#pragma unroll
        for (int j = 0; j < 4; j++) {
            int col = colBase + warpN + j * 8 + tc;
            float b0 = bbias ? bbias[col] : 0.f;
            float b1 = bbias ? bbias[col + 1] : 0.f;
            float v0 = acc[i][j][0] + b0, v1 = acc[i][j][1] + b1;
            float v2 = acc[i][j][2] + b0, v3 = acc[i][j][3] + b1;
            if (mode & 1) {
                v0 = (v0 > 0.f) ? v0 : 0.01f * v0;
                v1 = (v1 > 0.f) ? v1 : 0.01f * v1;
                v2 = (v2 > 0.f) ? v2 : 0.01f * v2;
                v3 = (v3 > 0.f) ? v3 : 0.01f * v3;
            }
            v0 *= scale; v1 *= scale; v2 *= scale; v3 *= scale;
            if (r0 < M) {
                float* p = C + (size_t)r0 * 256 + col;
                if (mode & 2) { v0 += p[0]; v1 += p[1]; }
                *(float2*)p = make_float2(v0, v1);
            }
            if (r0 + 8 < M) {
                float* p = C + (size_t)(r0 + 8) * 256 + col;
                if (mode & 2) { v2 += p[0]; v3 += p[1]; }
                *(float2*)p = make_float2(v2, v3);
            }
            if (mode & 4) {
                float s0 = attS[col], s1 = attS[col + 1];
                float d0 = attD[col], d1 = attD[col + 1];
                as0 += v0 * s0 + v1 * s1;  ad0 += v0 * d0 + v1 * d1;
                as1 += v2 * s0 + v3 * s1;  ad1 += v2 * d0 + v3 * d1;
            }
        }
        if (mode & 4) {
#pragma unroll
            for (int o = 1; o <= 2; o <<= 1) {
                as0 += __shfl_xor_sync(0xffffffffu, as0, o);
                ad0 += __shfl_xor_sync(0xffffffffu, ad0, o);
                as1 += __shfl_xor_sync(0xffffffffu, as1, o);
                ad1 += __shfl_xor_sync(0xffffffffu, ad1, o);
            }
            if ((lane & 3) == 0) {
                if (r0 < M)     { g_as[(size_t)r0 * 8 + head] = as0;       g_ad[(size_t)r0 * 8 + head] = ad0; }
                if (r0 + 8 < M) { g_as[(size_t)(r0 + 8) * 8 + head] = as1; g_ad[(size_t)(r0 + 8) * 8 + head] = ad1; }
            }
        }
    }
}

// ---------------- init m=-inf, s=0, agg=0 ----------------
__global__ void init_kernel()
{
    int i = blockIdx.x * blockDim.x + threadIdx.x;
    float4 z = make_float4(0.f, 0.f, 0.f, 0.f);
    if (i < Nn * 64) ((float4*)g_agg)[i] = z;
    if (i < Nn * 2) {
        ((float4*)g_s)[i] = z;
        float mi = __int_as_float(0xff800000);
        ((float4*)g_m)[i] = make_float4(mi, mi, mi, mi);
    }
}

__device__ __forceinline__ void atomicMaxF(float* a, float v)
{
    if (v >= 0.f) atomicMax((int*)a, __float_as_int(v));
    else          atomicMin((unsigned int*)a, __float_as_uint(v));
}

// ---------------- edge pass 1 ----------------
__global__ void edge1_kernel(const int* __restrict__ src, const int* __restrict__ dst)
{
    int e = blockIdx.x * blockDim.x + threadIdx.x;
    if (e >= Ee) return;
    int s = src[e], d = dst[e];
    const float4* aps = (const float4*)(g_as + (size_t)s * 8);
    const float4* apd = (const float4*)(g_ad + (size_t)d * 8);
    float4 s0 = aps[0], s1 = aps[1];
    float4 d0 = apd[0], d1 = apd[1];
    float v[8] = {s0.x + d0.x, s0.y + d0.y, s0.z + d0.z, s0.w + d0.w,
                  s1.x + d1.x, s1.y + d1.y, s1.z + d1.z, s1.w + d1.w};
    float* mrow = g_m + (size_t)d * 8;
#pragma unroll
    for (int h = 0; h < 8; h++) {
        float t = (v[h] > 0.f) ? v[h] : 0.2f * v[h];
        v[h] = t;
        atomicMaxF(mrow + h, t);
    }
    float4* ep = (float4*)(g_e + (size_t)e * 8);
    ep[0] = make_float4(v[0], v[1], v[2], v[3]);
    ep[1] = make_float4(v[4], v[5], v[6], v[7]);
}

// ---------------- edge pass 2 ----------------
__global__ void edge2_kernel(const int* __restrict__ dst)
{
    int e = blockIdx.x * blockDim.x + threadIdx.x;
    if (e >= Ee) return;
    int d = dst[e];
    float4* ep = (float4*)(g_e + (size_t)e * 8);
    float4 e0 = ep[0], e1 = ep[1];
    const float4* mp = (const float4*)(g_m + (size_t)d * 8);
    float4 m0 = mp[0], m1 = mp[1];
    float v[8] = {__expf(e0.x - m0.x), __expf(e0.y - m0.y),
                  __expf(e0.z - m0.z), __expf(e0.w - m0.w),
                  __expf(e1.x - m1.x), __expf(e1.y - m1.y),
                  __expf(e1.z - m1.z), __expf(e1.w - m1.w)};
    float* srow = g_s + (size_t)d * 8;
#pragma unroll
    for (int h = 0; h < 8; h++) atomicAdd(srow + h, v[h]);
    ep[0] = make_float4(v[0], v[1], v[2], v[3]);
    ep[1] = make_float4(v[4], v[5], v[6], v[7]);
}

// ---------------- edge pass 3: scatter messages; warp per edge ----------------
__global__ void edge3_kernel(const int* __restrict__ src, const int* __restrict__ dst)
{
    int gt = blockIdx.x * blockDim.x + threadIdx.x;
    int e = gt >> 5;
    int lane = gt & 31;
    if (e >= Ee) return;
    int s = src[e], d = dst[e];
    int c0 = lane * 4;
    int c1 = 128 + lane * 4;
    int h0 = lane >> 3;
    int h1 = 4 + (lane >> 3);
    float a0 = g_e[(size_t)e * 8 + h0] / (g_s[(size_t)d * 8 + h0] + 1e-16f);
    float a1 = g_e[(size_t)e * 8 + h1] / (g_s[(size_t)d * 8 + h1] + 1e-16f);
    const float* hs = g_h1 + (size_t)s * 256;
    float* ag = g_agg + (size_t)d * 256;
    float4 v0 = *(const float4*)(hs + c0);
    float4 v1 = *(const float4*)(hs + c1);
    v0.x *= a0; v0.y *= a0; v0.z *= a0; v0.w *= a0;
    v1.x *= a1; v1.y *= a1; v1.z *= a1; v1.w *= a1;
    atomicAdd((float4*)(ag + c0), v0);
    atomicAdd((float4*)(ag + c1), v1);
}

// ---------------- layernorm + residual: warp per node ----------------
__global__ void ln_kernel(const float* __restrict__ acc,
                          const float* __restrict__ scale,
                          const float* __restrict__ bias,
                          const float* __restrict__ res,
                          float* __restrict__ out)
{
    int gt = blockIdx.x * blockDim.x + threadIdx.x;
    int n = gt >> 5;
    int lane = gt & 31;
    if (n >= Nn) return;
    const float* a = acc + (size_t)n * 256;
    float4 v0 = *(const float4*)(a + lane * 4);
    float4 v1 = *(const float4*)(a + 128 + lane * 4);
    float sm = v0.x + v0.y + v0.z + v0.w + v1.x + v1.y + v1.z + v1.w;
    float sq = v0.x * v0.x + v0.y * v0.y + v0.z * v0.z + v0.w * v0.w
             + v1.x * v1.x + v1.y * v1.y + v1.z * v1.z + v1.w * v1.w;
#pragma unroll
    for (int o = 16; o > 0; o >>= 1) {
        sm += __shfl_xor_sync(0xffffffffu, sm, o);
        sq += __shfl_xor_sync(0xffffffffu, sq, o);
    }
    float mu = sm * (1.f / 256.f);
    float var = sq * (1.f / 256.f) - mu * mu;
    float rstd = rsqrtf(var + 1e-5f);

    const float* rp = res + (size_t)n * 256;
    float4 r0 = *(const float4*)(rp + lane * 4);
    float4 r1 = *(const float4*)(rp + 128 + lane * 4);
    float4 sc0 = *(const float4*)(scale + lane * 4);
    float4 sc1 = *(const float4*)(scale + 128 + lane * 4);
    float4 b0 = *(const float4*)(bias + lane * 4);
    float4 b1 = *(const float4*)(bias + 128 + lane * 4);

    float4 o0, o1;
    o0.x = (v0.x - mu) * rstd * sc0.x + b0.x + r0.x;
    o0.y = (v0.y - mu) * rstd * sc0.y + b0.y + r0.y;
    o0.z = (v0.z - mu) * rstd * sc0.z + b0.z + r0.z;
    o0.w = (v0.w - mu) * rstd * sc0.w + b0.w + r0.w;
    o1.x = (v1.x - mu) * rstd * sc1.x + b1.x + r1.x;
    o1.y = (v1.y - mu) * rstd * sc1.y + b1.y + r1.y;
    o1.z = (v1.z - mu) * rstd * sc1.z + b1.z + r1.z;
    o1.w = (v1.w - mu) * rstd * sc1.w + b1.w + r1.w;

    float* op = out + (size_t)n * 256;
    *(float4*)(op + lane * 4) = o0;
    *(float4*)(op + 128 + lane * 4) = o1;
}

// ---------------- host driver ----------------
extern "C" void kernel_launch(void* const* d_in, const int* in_sizes, int n_in,
                              void* d_out, int out_size)
{
    const float* x        = (const float*)d_in[0];
    const int*   edges    = (const int*)  d_in[1];
    const float* lin1_w   = (const float*)d_in[2];
    const float* lin1_b   = (const float*)d_in[3];
    const float* gat_w    = (const float*)d_in[4];
    const float* att_src  = (const float*)d_in[5];
    const float* att_dst  = (const float*)d_in[6];
    const float* gat_bias = (const float*)d_in[7];
    const float* dec_w    = (const float*)d_in[8];
    const float* dec_b    = (const float*)d_in[9];
    const float* ln_scale = (const float*)d_in[10];
    const float* ln_bias  = (const float*)d_in[11];
    float* out = (float*)d_out;

    static const float DECAY[3] = {1.0f, 0.60653065971263342f, 0.36787944117144233f};

    cudaFuncSetAttribute(gemm_mma, cudaFuncAttributeMaxDynamicSharedMemorySize, SM_TOTAL);

    float *p_h, *p_h1, *p_agg, *p_acc;
    cudaGetSymbolAddress((void**)&p_h,   g_h);
    cudaGetSymbolAddress((void**)&p_h1,  g_h1);
    cudaGetSymbolAddress((void**)&p_agg, g_agg);
    cudaGetSymbolAddress((void**)&p_acc, g_acc);

    // pre-convert 13 weight matrices to swizzled bf16 hi/lo
    convw_kernel<<<(1 * 65536 + 255) / 256, 256>>>(lin1_w, 1, 0);
    convw_kernel<<<(6 * 65536 + 255) / 256, 256>>>(gat_w, 6, 1);
    convw_kernel<<<(6 * 65536 + 255) / 256, 256>>>(dec_w, 6, 7);

    dim3 gg((Nn + 127) / 128, 2);

    // h = leaky(x @ lin1_w + lin1_b, 0.01)
    gemm_mma<<<gg, 256, SM_TOTAL>>>(x, 0, nullptr, lin1_b, nullptr, nullptr,
                                    p_h, Nn, 1, 1.f);

    for (int l = 0; l < 2; l++) {
        for (int k = 0; k < 3; k++) {
            int lk = l * 3 + k;
            // h1 = h @ W, fused alpha_src/alpha_dst
            gemm_mma<<<gg, 256, SM_TOTAL>>>(p_h, 1 + lk, nullptr, nullptr,
                                            att_src + (size_t)lk * 256,
                                            att_dst + (size_t)lk * 256,
                                            p_h1, Nn, 4, 1.f);
            init_kernel<<<(Nn * 64 + 255) / 256, 256>>>();

            const int* src = edges + (size_t)k * 2 * Ee;
            const int* dst = src + Ee;
            edge1_kernel<<<(Ee + 255) / 256, 256>>>(src, dst);
            edge2_kernel<<<(Ee + 255) / 256, 256>>>(dst);
            edge3_kernel<<<(Ee * 32 + 255) / 256, 256>>>(src, dst);

            // acc (k==0: =, else: +=) decay * leaky((agg + gat_bias) @ dec_w + dec_b)
            int mode = 1 | (k > 0 ? 2 : 0);
            gemm_mma<<<gg, 256, SM_TOTAL>>>(p_agg, 7 + lk,
                                            gat_bias + (size_t)lk * 256,
                                            dec_b + (size_t)lk * 256,
                                            nullptr, nullptr,
                                            p_acc, Nn, mode, DECAY[k]);
        }
        ln_kernel<<<(Nn * 32 + 255) / 256, 256>>>(
            p_acc, ln_scale + (size_t)l * 256, ln_bias + (size_t)l * 256,
            p_h, (l == 0) ? p_h : out);
    }
}